// round 9
// baseline (speedup 1.0000x reference)
#include <cuda_runtime.h>
#include <cuda_fp16.h>
#include <stdint.h>

// Problem constants
#define NPLANES 32            // B*C = 2*16
#define NTEX    512
#define HT      64
#define WT      64
#define TEXELS  (NTEX*HT*WT)  // 2,097,152 texels; plane stride in x
#define HO      1024
#define WO      1024
#define NPIX    (HO*WO)

#define TILE_T  256                    // texels per transpose tile
#define NTILES  (TEXELS / TILE_T)      // 8192 transpose tiles
#define NCHUNK  (NPIX / 256)           // 4096 chunks of 256 pixels
#define NSM     148                    // persistent grid (<= SM count, all co-resident)

// 128 MB transposed fp16 atlas. With the fused kernel it should stay almost
// entirely dirty-resident in L2 (126 MB) between the write (phase 1) and the
// random reads (phase 2).
__device__ __half g_xt_h[(size_t)TEXELS * NPLANES];

// Monotone grid-barrier counter (never reset; replay-safe: each barrier use
// consumes one epoch of NSM tickets).
__device__ unsigned g_bar;

__global__ __launch_bounds__(1024, 1) void fused_kernel(
    const float*  __restrict__ x,
    const int*    __restrict__ qidx,
    const float2* __restrict__ uv,
    float*        __restrict__ out) {

    __shared__ union {
        float tile[32][TILE_T + 1];    // phase 1 staging (32.9 KB)
        float s[4][64][33];            // phase 2 staging (33.8 KB)
    } shm;

    const int tid  = threadIdx.x;
    const int w    = tid >> 5;         // warp 0..31 (phase 1: plane)
    const int lane = tid & 31;

    // ---------------- Phase 1: transpose + fp32->fp16 ----------------
    // x reads __ldcs (evict-first) so atlas write-allocates own L2.
    for (int tb = blockIdx.x; tb < NTILES; tb += NSM) {
        const int tbase = tb * TILE_T;

        const float4* src4 = (const float4*)(x + (size_t)w * TEXELS + tbase);
        const float4 a = __ldcs(&src4[lane]);
        const float4 b = __ldcs(&src4[32 + lane]);
        {
            const int t0 = lane * 4;
            shm.tile[w][t0 + 0] = a.x; shm.tile[w][t0 + 1] = a.y;
            shm.tile[w][t0 + 2] = a.z; shm.tile[w][t0 + 3] = a.w;
            const int t1 = (32 + lane) * 4;
            shm.tile[w][t1 + 0] = b.x; shm.tile[w][t1 + 1] = b.y;
            shm.tile[w][t1 + 2] = b.z; shm.tile[w][t1 + 3] = b.w;
        }
        __syncthreads();

        const int tq = lane >> 3;
        const int c  = lane & 7;
        #pragma unroll
        for (int jj = 0; jj < 2; jj++) {
            const int t = w * 8 + jj * 4 + tq;
            const float v0 = shm.tile[4 * c + 0][t];
            const float v1 = shm.tile[4 * c + 1][t];
            const float v2 = shm.tile[4 * c + 2][t];
            const float v3 = shm.tile[4 * c + 3][t];
            const __half2 h0 = __floats2half2_rn(v0, v1);
            const __half2 h1 = __floats2half2_rn(v2, v3);
            uint2 pk;
            pk.x = *(const unsigned int*)&h0;
            pk.y = *(const unsigned int*)&h1;
            *(uint2*)(g_xt_h + (size_t)(tbase + t) * NPLANES + 4 * c) = pk;
        }
        __syncthreads();
    }

    // ---------------- Grid barrier (all 148 blocks co-resident) ----------------
    __threadfence();                   // release: my atlas stores visible GPU-wide
    __syncthreads();                   // all threads of block fenced before arrive
    if (tid == 0) {
        const unsigned ticket = atomicAdd(&g_bar, 1u);
        const unsigned target = (ticket / NSM + 1u) * NSM;
        while (*(volatile unsigned*)&g_bar < target) { __nanosleep(64); }
        __threadfence();               // acquire: other blocks' stores visible
    }
    __syncthreads();                   // propagate to whole block

    // ---------------- Phase 2: bilinear gather ----------------
    const int g    = tid >> 8;         // 256-thread group 0..3
    const int gw   = (tid >> 5) & 7;   // warp within group
    const int half = lane >> 4;
    const int j    = lane & 15;

    const __half2* atlas = (const __half2*)g_xt_h;

    for (int chunk = blockIdx.x; chunk < NCHUNK; chunk += NSM) {
        const int pixbase = chunk * 256 + g * 64;

        int    rn[4];
        float2 ruv[4];
        #pragma unroll
        for (int i = 0; i < 4; i++) {
            const int pix = pixbase + gw * 8 + i * 2 + half;
            rn[i]  = __ldcs(&qidx[pix]);
            ruv[i] = __ldcs(&uv[pix]);
        }

        #pragma unroll
        for (int i = 0; i < 4; i++) {
            const int pl = gw * 8 + i * 2 + half;

            int n = min(max(rn[i], 0), NTEX - 1);
            const float2 t = ruv[i];
            const float  u  = t.x * 63.0f;
            const float  v  = t.y * 63.0f;
            const float  x0f = floorf(u);
            const float  y0f = floorf(v);
            const float  wu  = u - x0f;
            const float  wv  = v - y0f;

            int x0 = (int)x0f; x0 = min(max(x0, 0), WT - 1);
            int y0 = (int)y0f; y0 = min(max(y0, 0), HT - 1);
            const int x1 = min(x0 + 1, WT - 1);
            const int y1 = min(y0 + 1, HT - 1);

            const int rb = n * (HT * WT);
            const int r0 = rb + y0 * WT;
            const int r1 = rb + y1 * WT;

            const float2 g00 = __half22float2(atlas[(size_t)(r0 + x0) * 16 + j]);
            const float2 g01 = __half22float2(atlas[(size_t)(r0 + x1) * 16 + j]);
            const float2 g10 = __half22float2(atlas[(size_t)(r1 + x0) * 16 + j]);
            const float2 g11 = __half22float2(atlas[(size_t)(r1 + x1) * 16 + j]);

            const float topx = fmaf(wu, g01.x - g00.x, g00.x);
            const float botx = fmaf(wu, g11.x - g10.x, g10.x);
            const float topy = fmaf(wu, g01.y - g00.y, g00.y);
            const float boty = fmaf(wu, g11.y - g10.y, g10.y);

            shm.s[g][pl][2 * j]     = fmaf(wv, botx - topx, topx);
            shm.s[g][pl][2 * j + 1] = fmaf(wv, boty - topy, topy);
        }

        __syncthreads();

        #pragma unroll
        for (int jj = 0; jj < 4; jj++) {
            const int p = gw * 4 + jj;
            float* o = out + (size_t)p * NPIX + pixbase;
            __stwt(&o[lane],      shm.s[g][lane][p]);
            __stwt(&o[32 + lane], shm.s[g][32 + lane][p]);
        }
        __syncthreads();
    }
}

extern "C" void kernel_launch(void* const* d_in, const int* in_sizes, int n_in,
                              void* d_out, int out_size) {
    const float*  x    = (const float*)d_in[0];
    const int*    qidx = (const int*)d_in[1];
    const float2* uv   = (const float2*)d_in[2];
    float*        out  = (float*)d_out;

    fused_kernel<<<NSM, 1024>>>(x, qidx, uv, out);
}